// round 16
// baseline (speedup 1.0000x reference)
#include <cuda_runtime.h>
#include <cuda_bf16.h>

#define FULLM 0xFFFFFFFFu

constexpr int B_ = 8;
constexpr int N_ = 2048;
constexpr int K_ = 32;
constexpr int CO_ = 64;
constexpr int ROWS_ = B_ * N_;   // 16384
constexpr int CAP_ = 512;        // survivor cap per row

// ---------------- static scratch (no allocation) ----------------
__device__ float    d_sq[ROWS_];
__device__ unsigned d_dist[(size_t)ROWS_ * N_];   // f2u-transformed distances
__device__ unsigned d_gmin[ROWS_ * 32];           // per-row mins of 32 column-groups
__device__ int      d_idx[ROWS_ * K_];
__device__ float    d_h [ROWS_ * CO_];
__device__ float    d_mx[ROWS_ * CO_];
__device__ float    d_mn[ROWS_ * CO_];
__device__ float    d_sum[CO_];
__device__ float    d_ssq[CO_];
__device__ float    d_scale[CO_];
__device__ float    d_shift[CO_];
__device__ float    d_wd2[64 * 64];
__device__ float    d_wf2[64 * 64];

// ---------------- packed fp32x2 helpers ----------------
__device__ __forceinline__ unsigned long long pk2(float v) {
    unsigned long long r;
    asm("mov.b64 %0, {%1, %1};" : "=l"(r) : "f"(v));
    return r;
}
__device__ __forceinline__ void fma2(unsigned long long& d, unsigned long long a, unsigned long long b) {
    asm("fma.rn.f32x2 %0, %1, %2, %0;" : "+l"(d) : "l"(a), "l"(b));
}
__device__ __forceinline__ float2 up2(unsigned long long v) {
    float2 r;
    asm("mov.b64 {%0, %1}, %2;" : "=f"(r.x), "=f"(r.y) : "l"(v));
    return r;
}

// order-preserving float -> uint (ascending)
__device__ __forceinline__ unsigned f2u(float f) {
    unsigned u = __float_as_uint(f);
    return u ^ ((unsigned)((int)u >> 31) | 0x80000000u);
}

// ---------------- exact warp argmax on u64 (dist<<32|col) keys via 2x REDUX ----------------
__device__ __forceinline__ void warp_argmax64(unsigned long long v, int l,
                                              unsigned long long& mv, int& ml) {
    unsigned hi = (unsigned)(v >> 32);
    unsigned hmax = __reduce_max_sync(FULLM, hi);
    unsigned lo = (hi == hmax) ? (unsigned)v : 0u;
    unsigned lmax = __reduce_max_sync(FULLM, lo);
    ml = __ffs(__ballot_sync(FULLM, (hi == hmax) & ((unsigned)v == lmax))) - 1;
    mv = ((unsigned long long)hmax << 32) | lmax;
}

__device__ __forceinline__ void insert64(unsigned long long cand,
                                         unsigned long long& cur,
                                         unsigned long long& cmax, int& cml, int l) {
    unsigned m = __ballot_sync(FULLM, cand < cmax);
    while (m) {
        int s = __ffs(m) - 1;
        unsigned long long cn = __shfl_sync(FULLM, cand, s);
        if (l == cml) cur = cn;
        warp_argmax64(cur, l, cmax, cml);
        m &= ~(1u << s);
        m &= __ballot_sync(FULLM, cand < cmax);
    }
}

// ---------------- squared norms for stage 1 (+ stats zeroing) ----------------
__global__ void sqnorm3_kernel(const float* __restrict__ a) {
    if (blockIdx.x == 0 && threadIdx.x < CO_) {
        d_sum[threadIdx.x] = 0.f;
        d_ssq[threadIdx.x] = 0.f;
    }
    int i = blockIdx.x * blockDim.x + threadIdx.x;
    if (i >= ROWS_) return;
    const float* p = a + (size_t)i * 3;
    d_sq[i] = p[0]*p[0] + p[1]*p[1] + p[2]*p[2];
}

// ---------------- distance GEMM: 128 rows x 512 cols per block, 16 rows/warp ----------------
template<int C>
__global__ void __launch_bounds__(256) dist_kernel(const float* __restrict__ xin) {
    const float* x = xin ? xin : (const float*)d_h;
    __shared__ __align__(16) float AT[C][132];
    __shared__ __align__(16) float BT[C][68];
    __shared__ float sqa[128], sqb[64];

    const int tid = threadIdx.x, w = tid >> 5, l = tid & 31;
    const int row0 = blockIdx.x * 128;
    const int cg   = blockIdx.y;
    const int b    = row0 >> 11;
    const int nb0  = row0 & (N_ - 1);
    const float* xb = x + (size_t)b * N_ * C;

    if (C == 3) {
        for (int v = tid; v < 384; v += 256) {
            int c = v >> 7, p = v & 127;
            AT[c][p] = xb[(size_t)(nb0 + p) * 3 + c];
        }
    } else {
        for (int v = tid; v < 128 * (C / 4); v += 256) {
            int c4 = v >> 7, p = v & 127;
            float4 f = *reinterpret_cast<const float4*>(xb + (size_t)(nb0 + p) * C + 4 * c4);
            AT[4*c4+0][p] = f.x; AT[4*c4+1][p] = f.y;
            AT[4*c4+2][p] = f.z; AT[4*c4+3][p] = f.w;
        }
    }
    if (tid < 128) sqa[tid] = d_sq[row0 + tid];

    for (int tile = 0; tile < 8; tile++) {
        const int col0 = cg * 512 + tile * 64;
        const int gidx = cg * 8 + tile;
        __syncthreads();
        if (C == 3) {
            for (int v = tid; v < 192; v += 256) {
                int c = v >> 6, p = v & 63;
                BT[c][p] = xb[(size_t)(col0 + p) * 3 + c];
            }
        } else {
            for (int v = tid; v < 64 * (C / 4); v += 256) {
                int c4 = v >> 6, p = v & 63;
                float4 f = *reinterpret_cast<const float4*>(xb + (size_t)(col0 + p) * C + 4 * c4);
                BT[4*c4+0][p] = f.x; BT[4*c4+1][p] = f.y;
                BT[4*c4+2][p] = f.z; BT[4*c4+3][p] = f.w;
            }
        }
        if (tid < 64) sqb[tid] = d_sq[b * N_ + col0 + tid];
        __syncthreads();

        // rows 16w..16w+15 (8 packed pairs) x cols (2l, 2l+1)
        unsigned long long acc[8][2];
#pragma unroll
        for (int i = 0; i < 8; i++) { acc[i][0] = 0ull; acc[i][1] = 0ull; }
#pragma unroll 4
        for (int c = 0; c < C; c++) {
            ulonglong2 a0 = *reinterpret_cast<const ulonglong2*>(&AT[c][16 * w]);
            ulonglong2 a1 = *reinterpret_cast<const ulonglong2*>(&AT[c][16 * w + 4]);
            ulonglong2 a2 = *reinterpret_cast<const ulonglong2*>(&AT[c][16 * w + 8]);
            ulonglong2 a3 = *reinterpret_cast<const ulonglong2*>(&AT[c][16 * w + 12]);
            float2 bb = up2(*reinterpret_cast<const unsigned long long*>(&BT[c][2 * l]));
            unsigned long long p0 = pk2(bb.x), p1 = pk2(bb.y);
            fma2(acc[0][0], a0.x, p0); fma2(acc[0][1], a0.x, p1);
            fma2(acc[1][0], a0.y, p0); fma2(acc[1][1], a0.y, p1);
            fma2(acc[2][0], a1.x, p0); fma2(acc[2][1], a1.x, p1);
            fma2(acc[3][0], a1.y, p0); fma2(acc[3][1], a1.y, p1);
            fma2(acc[4][0], a2.x, p0); fma2(acc[4][1], a2.x, p1);
            fma2(acc[5][0], a2.y, p0); fma2(acc[5][1], a2.y, p1);
            fma2(acc[6][0], a3.x, p0); fma2(acc[6][1], a3.x, p1);
            fma2(acc[7][0], a3.y, p0); fma2(acc[7][1], a3.y, p1);
        }

        float sb0 = sqb[2 * l], sb1 = sqb[2 * l + 1];
#pragma unroll
        for (int rp = 0; rp < 8; rp++) {
            float2 c0 = up2(acc[rp][0]);
            float2 c1 = up2(acc[rp][1]);
            int r = 16 * w + 2 * rp;
            float sa0 = sqa[r], sa1 = sqa[r + 1];
            uint2 o0, o1;
            o0.x = f2u(sa0 + sb0 - 2.f * c0.x);
            o0.y = f2u(sa0 + sb1 - 2.f * c1.x);
            o1.x = f2u(sa1 + sb0 - 2.f * c0.y);
            o1.y = f2u(sa1 + sb1 - 2.f * c1.y);
            *reinterpret_cast<uint2*>(&d_dist[(size_t)(row0 + r) * N_ + col0 + 2 * l])     = o0;
            *reinterpret_cast<uint2*>(&d_dist[(size_t)(row0 + r + 1) * N_ + col0 + 2 * l]) = o1;

            unsigned g0 = __reduce_min_sync(FULLM, min(o0.x, o0.y));
            unsigned g1 = __reduce_min_sync(FULLM, min(o1.x, o1.y));
            if (l == 0) {
                d_gmin[(row0 + r)     * 32 + gidx] = g0;
                d_gmin[(row0 + r + 1) * 32 + gidx] = g1;
            }
        }
    }
}

// ---------------- selection: warp/row, tau from d_gmin, ONE sweep + ballot compact + insert ----------------
__device__ void knn_fallback(const unsigned* __restrict__ dr, int row, int l) {
    unsigned long long cur = ((unsigned long long)dr[l] << 32) | (unsigned)l;
    unsigned long long cmax; int cml;
    warp_argmax64(cur, l, cmax, cml);
    for (int ch = 1; ch < 64; ch++) {
        int col = ch * 32 + l;
        unsigned long long cand = ((unsigned long long)dr[col] << 32) | (unsigned)col;
        insert64(cand, cur, cmax, cml, l);
    }
    d_idx[row * K_ + l] = (int)(unsigned)cur;
}

__global__ void __launch_bounds__(256) select_kernel() {
    __shared__ unsigned long long buf[8][CAP_];
    const int tid = threadIdx.x, w = tid >> 5, l = tid & 31;
    const int row = blockIdx.x * 8 + w;
    const unsigned* dr = d_dist + (size_t)row * N_;

    unsigned tau = __reduce_max_sync(FULLM, d_gmin[row * 32 + l]);

    int cnt = 0;
    for (int j = 0; j < 16; j++) {
        uint4 v = *reinterpret_cast<const uint4*>(dr + 4 * l + 128 * j);
        unsigned e[4] = {v.x, v.y, v.z, v.w};
#pragma unroll
        for (int q = 0; q < 4; q++) {
            bool p = e[q] <= tau;
            unsigned m = __ballot_sync(FULLM, p);
            if (p) {
                int pos = cnt + __popc(m & ((1u << l) - 1u));
                if (pos < CAP_)
                    buf[w][pos] = ((unsigned long long)e[q] << 32) | (unsigned)(4 * l + 128 * j + q);
            }
            cnt += __popc(m);
        }
    }
    if (cnt > CAP_) { knn_fallback(dr, row, l); return; }

    unsigned long long cur = buf[w][l];
    unsigned long long cmax; int cml;
    warp_argmax64(cur, l, cmax, cml);
    for (int base = 32; base < cnt; base += 32) {
        int ix = base + l;
        unsigned long long cand = (ix < cnt) ? buf[w][ix] : ~0ull;
        insert64(cand, cur, cmax, cml, l);
    }
    d_idx[row * K_ + l] = (int)(unsigned)cur;
}

// ---------------- stats finalize ----------------
__global__ void finalize_kernel(const float* __restrict__ gamma, const float* __restrict__ beta) {
    int o = threadIdx.x;
    if (o < CO_) {
        float cnt  = (float)(B_ * N_ * K_);
        float mean = d_sum[o] / cnt;
        float var  = d_ssq[o] / cnt - mean * mean;
        float sc   = gamma[o] * rsqrtf(var + 1e-5f);
        d_scale[o] = sc;
        d_shift[o] = beta[o] - mean * sc;
    }
}

// ---------------- weight prep for stage 2 ----------------
__global__ void prep_kernel(const float* __restrict__ W2) {
    int t = blockIdx.x * 256 + threadIdx.x;
    if (t < 4096) {
        int c = t >> 6, o = t & 63;
        float wd = W2[o * 128 + c];
        d_wd2[t] = wd;
        d_wf2[t] = W2[o * 128 + 64 + c] - wd;
    }
}

// ---------------- conv stage 1 (CIN=3): warp per point ----------------
__global__ void __launch_bounds__(256) conv3_kernel(const float* __restrict__ a,
                                                    const float* __restrict__ W) {
    __shared__ float snb[8][3][33];
    __shared__ float cs[64], css[64];
    const int tid = threadIdx.x, w = tid >> 5, l = tid & 31;
    const int pt = blockIdx.x * 8 + w;
    const int b  = pt >> 11, n = pt & (N_ - 1);
    const size_t pbase = (size_t)b * N_;

    if (tid < 64) { cs[tid] = 0.f; css[tid] = 0.f; }

    int nb = d_idx[(pbase + n) * K_ + l];
    const float* xp = a + (pbase + nb) * 3;
    snb[w][0][l] = xp[0]; snb[w][1][l] = xp[1]; snb[w][2][l] = xp[2];

    const float* cp = a + (pbase + n) * 3;
    float cx = cp[0], cy = cp[1], cz = cp[2];

    float wd[2][3], bse[2];
#pragma unroll
    for (int h = 0; h < 2; h++) {
        const float* wr = W + (2 * l + h) * 6;
        wd[h][0] = wr[0]; wd[h][1] = wr[1]; wd[h][2] = wr[2];
        bse[h] = cx * (wr[3] - wr[0]) + cy * (wr[4] - wr[1]) + cz * (wr[5] - wr[2]);
    }
    __syncwarp();
    __syncthreads();

    float s0 = 0.f, ss0 = 0.f, mx0 = -3.4e38f, mn0 = 3.4e38f;
    float s1 = 0.f, ss1 = 0.f, mx1 = -3.4e38f, mn1 = 3.4e38f;
#pragma unroll 8
    for (int r = 0; r < 32; r++) {
        float nx = snb[w][0][r], ny = snb[w][1][r], nz = snb[w][2][r];
        float y0 = fmaf(nz, wd[0][2], fmaf(ny, wd[0][1], nx * wd[0][0])) + bse[0];
        float y1 = fmaf(nz, wd[1][2], fmaf(ny, wd[1][1], nx * wd[1][0])) + bse[1];
        s0 += y0; ss0 = fmaf(y0, y0, ss0); mx0 = fmaxf(mx0, y0); mn0 = fminf(mn0, y0);
        s1 += y1; ss1 = fmaf(y1, y1, ss1); mx1 = fmaxf(mx1, y1); mn1 = fminf(mn1, y1);
    }
    size_t gi = (pbase + n) * 64 + 2 * l;
    d_mx[gi] = mx0; d_mx[gi + 1] = mx1;
    d_mn[gi] = mn0; d_mn[gi + 1] = mn1;

    atomicAdd(&cs [2 * l], s0);  atomicAdd(&cs [2 * l + 1], s1);
    atomicAdd(&css[2 * l], ss0); atomicAdd(&css[2 * l + 1], ss1);
    __syncthreads();
    if (tid < 64) {
        atomicAdd(&d_sum[tid], cs[tid]);
        atomicAdd(&d_ssq[tid], css[tid]);
    }
}

// ---------------- conv stage 2 (CIN=64): 4 points/block, 4x8 thread tile, high occupancy ----------------
constexpr int CP_ = 132;   // bufT row stride (floats), 16B-aligned

__global__ void __launch_bounds__(256, 4) conv64_kernel() {
    __shared__ __align__(16) float bufT[64][CP_];   // [c][row 0..127], 33.8 KB; reused for stats
    __shared__ __align__(16) float swd[64][68];     // 17.4 KB
    __shared__ float cen[4][64];
    __shared__ float bs[4][64];
    __shared__ int   sidx[128];
    __shared__ float cs[64], css[64];

    const float* x = (const float*)d_h;
    const int tid = threadIdx.x;
    const int pid = blockIdx.x;          // 4096 blocks
    const int b   = pid >> 9;
    const int n0  = (pid & 511) * 4;
    const size_t base = (size_t)b * N_;

    if (tid < 64) { cs[tid] = 0.f; css[tid] = 0.f; }
    if (tid < 128) sidx[tid] = d_idx[(base + n0 + (tid >> 5)) * K_ + (tid & 31)];
    for (int v = tid; v < 4096; v += 256) swd[v >> 6][v & 63] = d_wd2[v];
    if (tid < 256) {
        int p = tid >> 6, c = tid & 63;
        cen[p][c] = x[(base + n0 + p) * 64 + c];
    }
    __syncthreads();

    // gather neighbor features, transposed
    for (int v = tid; v < 2048; v += 256) {
        int c4 = v >> 7, r = v & 127;
        float4 f = *reinterpret_cast<const float4*>(x + (base + sidx[r]) * 64 + 4 * c4);
        bufT[4*c4+0][r] = f.x; bufT[4*c4+1][r] = f.y;
        bufT[4*c4+2][r] = f.z; bufT[4*c4+3][r] = f.w;
    }
    // center term: read d_wf2 directly from global (coalesced, L2-resident)
    {
        int p = tid >> 6, o = tid & 63;
        float t = 0.f;
#pragma unroll 8
        for (int c = 0; c < 64; c++) t = fmaf(cen[p][c], d_wf2[c * 64 + o], t);
        bs[p][o] = t;
    }
    __syncthreads();

    // GEMM: thread -> rows 4rg..4rg+3 x cols 8g..8g+7 (cols packed in pairs)
    const int rg = tid >> 3, g = tid & 7;
    const int r0 = rg * 4;
    unsigned long long acc[4][4];
#pragma unroll
    for (int i = 0; i < 4; i++)
#pragma unroll
        for (int j = 0; j < 4; j++) acc[i][j] = 0ull;

#pragma unroll 4
    for (int c = 0; c < 64; c++) {
        float4 a0 = *reinterpret_cast<const float4*>(&bufT[c][r0]);
        ulonglong2 w01 = *reinterpret_cast<const ulonglong2*>(&swd[c][8 * g]);
        ulonglong2 w23 = *reinterpret_cast<const ulonglong2*>(&swd[c][8 * g + 4]);
        unsigned long long pa[4] = {pk2(a0.x), pk2(a0.y), pk2(a0.z), pk2(a0.w)};
#pragma unroll
        for (int i = 0; i < 4; i++) {
            fma2(acc[i][0], pa[i], w01.x);
            fma2(acc[i][1], pa[i], w01.y);
            fma2(acc[i][2], pa[i], w23.x);
            fma2(acc[i][3], pa[i], w23.y);
        }
    }
    __syncthreads();   // bufT reads done; reuse as stats storage

    float* st0 = &bufT[0][0];         // [32][64] each (8448 floats available >= 8192)
    float* st1 = st0 + 2048;
    float* st2 = st0 + 4096;
    float* st3 = st0 + 6144;

    // per-thread partial stats over its 4 rows, per col
#pragma unroll
    for (int cp = 0; cp < 4; cp++) {
        float s_x = 0.f, ss_x = 0.f, mx_x = -3.4e38f, mn_x = 3.4e38f;
        float s_y = 0.f, ss_y = 0.f, mx_y = -3.4e38f, mn_y = 3.4e38f;
#pragma unroll
        for (int i = 0; i < 4; i++) {
            float2 v = up2(acc[i][cp]);
            s_x += v.x; ss_x = fmaf(v.x, v.x, ss_x); mx_x = fmaxf(mx_x, v.x); mn_x = fminf(mn_x, v.x);
            s_y += v.y; ss_y = fmaf(v.y, v.y, ss_y); mx_y = fmaxf(mx_y, v.y); mn_y = fminf(mn_y, v.y);
        }
        int o0 = 8 * g + 2 * cp, o1 = o0 + 1;
        st0[rg * 64 + o0] = s_x;  st0[rg * 64 + o1] = s_y;
        st1[rg * 64 + o0] = ss_x; st1[rg * 64 + o1] = ss_y;
        st2[rg * 64 + o0] = mx_x; st2[rg * 64 + o1] = mx_y;
        st3[rg * 64 + o0] = mn_x; st3[rg * 64 + o1] = mn_y;
    }
    __syncthreads();

    // combine 8 row-groups per point, add base, emit
    {
        int p = tid >> 6, o = tid & 63;
        float S = 0.f, SS = 0.f, MX = -3.4e38f, MN = 3.4e38f;
#pragma unroll
        for (int q = 0; q < 8; q++) {
            int rr = 8 * p + q;
            S  += st0[rr * 64 + o];
            SS += st1[rr * 64 + o];
            MX  = fmaxf(MX, st2[rr * 64 + o]);
            MN  = fminf(MN, st3[rr * 64 + o]);
        }
        float bb = bs[p][o];
        size_t gi = (base + n0 + p) * 64 + o;
        d_mx[gi] = MX + bb;
        d_mn[gi] = MN + bb;
        atomicAdd(&cs[o],  S + 32.f * bb);
        atomicAdd(&css[o], SS + 2.f * bb * S + 32.f * bb * bb);
    }
    __syncthreads();
    if (tid < 64) {
        atomicAdd(&d_sum[tid], cs[tid]);
        atomicAdd(&d_ssq[tid], css[tid]);
    }
}

// ---------------- passb+sqnorm fused (stage1 -> d_h, d_sq; zeroes stage2 stats) ----------------
__global__ void __launch_bounds__(256) passb_sq_kernel() {
    const int tid = threadIdx.x, w = tid >> 5, l = tid & 31;
    const int pt = blockIdx.x * 8 + w;
    if (blockIdx.x == 0 && tid < CO_) { d_sum[tid] = 0.f; d_ssq[tid] = 0.f; }

    size_t gi = (size_t)pt * 64 + 2 * l;
    float2 mx = *reinterpret_cast<const float2*>(&d_mx[gi]);
    float2 mn = *reinterpret_cast<const float2*>(&d_mn[gi]);
    int o = 2 * l;
    float sc0 = d_scale[o],     sh0 = d_shift[o];
    float sc1 = d_scale[o + 1], sh1 = d_shift[o + 1];
    float y0 = sc0 * ((sc0 >= 0.f) ? mx.x : mn.x) + sh0;
    float y1 = sc1 * ((sc1 >= 0.f) ? mx.y : mn.y) + sh1;
    y0 = (y0 >= 0.f) ? y0 : 0.2f * y0;
    y1 = (y1 >= 0.f) ? y1 : 0.2f * y1;
    *reinterpret_cast<float2*>(&d_h[gi]) = make_float2(y0, y1);

    float s = y0 * y0 + y1 * y1;
#pragma unroll
    for (int off = 16; off > 0; off >>= 1) s += __shfl_down_sync(FULLM, s, off);
    if (l == 0) d_sq[pt] = s;
}

// ---------------- pass B final (stage2 -> out) ----------------
__global__ void passb_kernel(float* __restrict__ out) {
    int e = blockIdx.x * 256 + threadIdx.x;
    if (e >= ROWS_ * CO_) return;
    int o = e & 63;
    float sc = d_scale[o];
    float v  = (sc >= 0.f) ? d_mx[e] : d_mn[e];
    float y  = sc * v + d_shift[o];
    out[e] = (y >= 0.f) ? y : 0.2f * y;
}

// ---------------- launch ----------------
extern "C" void kernel_launch(void* const* d_in, const int* in_sizes, int n_in,
                              void* d_out, int out_size) {
    const float* a  = (const float*)d_in[0];
    const float* W1 = (const float*)d_in[2];
    const float* g1 = (const float*)d_in[3];
    const float* b1 = (const float*)d_in[4];
    const float* W2 = (const float*)d_in[5];
    const float* g2 = (const float*)d_in[6];
    const float* b2 = (const float*)d_in[7];
    float* out = (float*)d_out;

    dim3 dg(ROWS_ / 128, 4);
    int  pts = ROWS_;

    prep_kernel<<<16, 256>>>(W2);

    // stage 1 (C = 3)
    sqnorm3_kernel<<<(pts + 255) / 256, 256>>>(a);   // also zeroes stage-1 stats
    dist_kernel<3><<<dg, 256>>>(a);
    select_kernel<<<pts / 8, 256>>>();
    conv3_kernel<<<pts / 8, 256>>>(a, W1);
    finalize_kernel<<<1, 64>>>(g1, b1);
    passb_sq_kernel<<<pts / 8, 256>>>();             // d_h + d_sq + zero stage-2 stats

    // stage 2 (C = 64)
    dist_kernel<64><<<dg, 256>>>(nullptr);
    select_kernel<<<pts / 8, 256>>>();
    conv64_kernel<<<pts / 4, 256>>>();
    finalize_kernel<<<1, 64>>>(g2, b2);
    passb_kernel<<<(pts * CO_ + 255) / 256, 256>>>(out);
}

// round 17
// speedup vs baseline: 1.1218x; 1.1218x over previous
#include <cuda_runtime.h>
#include <cuda_bf16.h>

#define FULLM 0xFFFFFFFFu

constexpr int B_ = 8;
constexpr int N_ = 2048;
constexpr int K_ = 32;
constexpr int CO_ = 64;
constexpr int ROWS_ = B_ * N_;   // 16384
constexpr int CAP_ = 512;        // survivor cap per row

// ---------------- static scratch (no allocation) ----------------
__device__ float    d_sq[ROWS_];                  // stage-2 feature sqnorms (stage-1 inline in dist3)
__device__ unsigned d_dist[(size_t)ROWS_ * N_];   // f2u-transformed distances
__device__ unsigned d_gmin[ROWS_ * 32];           // per-row mins of 32 column-groups
__device__ int      d_idx[ROWS_ * K_];
__device__ float    d_h [ROWS_ * CO_];
__device__ float    d_mx[ROWS_ * CO_];
__device__ float    d_mn[ROWS_ * CO_];
__device__ float    d_sum [CO_], d_ssq [CO_];     // stage-1 stats
__device__ float    d_sum2[CO_], d_ssq2[CO_];     // stage-2 stats
__device__ float    d_wd2[64 * 64];
__device__ float    d_wf2[64 * 64];

// ---------------- packed fp32x2 helpers ----------------
__device__ __forceinline__ unsigned long long pk2(float v) {
    unsigned long long r;
    asm("mov.b64 %0, {%1, %1};" : "=l"(r) : "f"(v));
    return r;
}
__device__ __forceinline__ void fma2(unsigned long long& d, unsigned long long a, unsigned long long b) {
    asm("fma.rn.f32x2 %0, %1, %2, %0;" : "+l"(d) : "l"(a), "l"(b));
}
__device__ __forceinline__ float2 up2(unsigned long long v) {
    float2 r;
    asm("mov.b64 {%0, %1}, %2;" : "=f"(r.x), "=f"(r.y) : "l"(v));
    return r;
}

// order-preserving float -> uint (ascending)
__device__ __forceinline__ unsigned f2u(float f) {
    unsigned u = __float_as_uint(f);
    return u ^ ((unsigned)((int)u >> 31) | 0x80000000u);
}

// ---------------- exact warp argmax on u64 (dist<<32|col) keys via 2x REDUX ----------------
__device__ __forceinline__ void warp_argmax64(unsigned long long v, int l,
                                              unsigned long long& mv, int& ml) {
    unsigned hi = (unsigned)(v >> 32);
    unsigned hmax = __reduce_max_sync(FULLM, hi);
    unsigned lo = (hi == hmax) ? (unsigned)v : 0u;
    unsigned lmax = __reduce_max_sync(FULLM, lo);
    ml = __ffs(__ballot_sync(FULLM, (hi == hmax) & ((unsigned)v == lmax))) - 1;
    mv = ((unsigned long long)hmax << 32) | lmax;
}

__device__ __forceinline__ void insert64(unsigned long long cand,
                                         unsigned long long& cur,
                                         unsigned long long& cmax, int& cml, int l) {
    unsigned m = __ballot_sync(FULLM, cand < cmax);
    while (m) {
        int s = __ffs(m) - 1;
        unsigned long long cn = __shfl_sync(FULLM, cand, s);
        if (l == cml) cur = cn;
        warp_argmax64(cur, l, cmax, cml);
        m &= ~(1u << s);
        m &= __ballot_sync(FULLM, cand < cmax);
    }
}

// ---------------- prep: weight transform + zero both stat sets ----------------
__global__ void prep_kernel(const float* __restrict__ W2) {
    int t = blockIdx.x * 256 + threadIdx.x;
    if (t < CO_) { d_sum[t] = 0.f; d_ssq[t] = 0.f; d_sum2[t] = 0.f; d_ssq2[t] = 0.f; }
    if (t < 4096) {
        int c = t >> 6, o = t & 63;
        float wd = W2[o * 128 + c];
        d_wd2[t] = wd;
        d_wf2[t] = W2[o * 128 + 64 + c] - wd;
    }
}

// ---------------- distance GEMM: 128 rows x 512 cols per block, 16 rows/warp ----------------
// C==3: sqnorms computed inline from the loaded tiles (no d_sq dependency)
template<int C>
__global__ void __launch_bounds__(256) dist_kernel(const float* __restrict__ xin) {
    const float* x = xin ? xin : (const float*)d_h;
    __shared__ __align__(16) float AT[C][132];
    __shared__ __align__(16) float BT[C][68];
    __shared__ float sqa[128], sqb[64];

    const int tid = threadIdx.x, w = tid >> 5, l = tid & 31;
    const int row0 = blockIdx.x * 128;
    const int cg   = blockIdx.y;
    const int b    = row0 >> 11;
    const int nb0  = row0 & (N_ - 1);
    const float* xb = x + (size_t)b * N_ * C;

    if (C == 3) {
        for (int v = tid; v < 384; v += 256) {
            int c = v >> 7, p = v & 127;
            AT[c][p] = xb[(size_t)(nb0 + p) * 3 + c];
        }
    } else {
        for (int v = tid; v < 128 * (C / 4); v += 256) {
            int c4 = v >> 7, p = v & 127;
            float4 f = *reinterpret_cast<const float4*>(xb + (size_t)(nb0 + p) * C + 4 * c4);
            AT[4*c4+0][p] = f.x; AT[4*c4+1][p] = f.y;
            AT[4*c4+2][p] = f.z; AT[4*c4+3][p] = f.w;
        }
    }
    __syncthreads();
    if (tid < 128) {
        if (C == 3)
            sqa[tid] = AT[0][tid]*AT[0][tid] + AT[1][tid]*AT[1][tid] + AT[2][tid]*AT[2][tid];
        else
            sqa[tid] = d_sq[row0 + tid];
    }

    for (int tile = 0; tile < 8; tile++) {
        const int col0 = cg * 512 + tile * 64;
        const int gidx = cg * 8 + tile;
        __syncthreads();
        if (C == 3) {
            for (int v = tid; v < 192; v += 256) {
                int c = v >> 6, p = v & 63;
                BT[c][p] = xb[(size_t)(col0 + p) * 3 + c];
            }
        } else {
            for (int v = tid; v < 64 * (C / 4); v += 256) {
                int c4 = v >> 6, p = v & 63;
                float4 f = *reinterpret_cast<const float4*>(xb + (size_t)(col0 + p) * C + 4 * c4);
                BT[4*c4+0][p] = f.x; BT[4*c4+1][p] = f.y;
                BT[4*c4+2][p] = f.z; BT[4*c4+3][p] = f.w;
            }
        }
        __syncthreads();
        if (tid < 64) {
            if (C == 3)
                sqb[tid] = BT[0][tid]*BT[0][tid] + BT[1][tid]*BT[1][tid] + BT[2][tid]*BT[2][tid];
            else
                sqb[tid] = d_sq[b * N_ + col0 + tid];
        }
        __syncthreads();

        // rows 16w..16w+15 (8 packed pairs) x cols (2l, 2l+1)
        unsigned long long acc[8][2];
#pragma unroll
        for (int i = 0; i < 8; i++) { acc[i][0] = 0ull; acc[i][1] = 0ull; }
#pragma unroll 4
        for (int c = 0; c < C; c++) {
            ulonglong2 a0 = *reinterpret_cast<const ulonglong2*>(&AT[c][16 * w]);
            ulonglong2 a1 = *reinterpret_cast<const ulonglong2*>(&AT[c][16 * w + 4]);
            ulonglong2 a2 = *reinterpret_cast<const ulonglong2*>(&AT[c][16 * w + 8]);
            ulonglong2 a3 = *reinterpret_cast<const ulonglong2*>(&AT[c][16 * w + 12]);
            float2 bb = up2(*reinterpret_cast<const unsigned long long*>(&BT[c][2 * l]));
            unsigned long long p0 = pk2(bb.x), p1 = pk2(bb.y);
            fma2(acc[0][0], a0.x, p0); fma2(acc[0][1], a0.x, p1);
            fma2(acc[1][0], a0.y, p0); fma2(acc[1][1], a0.y, p1);
            fma2(acc[2][0], a1.x, p0); fma2(acc[2][1], a1.x, p1);
            fma2(acc[3][0], a1.y, p0); fma2(acc[3][1], a1.y, p1);
            fma2(acc[4][0], a2.x, p0); fma2(acc[4][1], a2.x, p1);
            fma2(acc[5][0], a2.y, p0); fma2(acc[5][1], a2.y, p1);
            fma2(acc[6][0], a3.x, p0); fma2(acc[6][1], a3.x, p1);
            fma2(acc[7][0], a3.y, p0); fma2(acc[7][1], a3.y, p1);
        }

        float sb0 = sqb[2 * l], sb1 = sqb[2 * l + 1];
#pragma unroll
        for (int rp = 0; rp < 8; rp++) {
            float2 c0 = up2(acc[rp][0]);
            float2 c1 = up2(acc[rp][1]);
            int r = 16 * w + 2 * rp;
            float sa0 = sqa[r], sa1 = sqa[r + 1];
            uint2 o0, o1;
            o0.x = f2u(sa0 + sb0 - 2.f * c0.x);
            o0.y = f2u(sa0 + sb1 - 2.f * c1.x);
            o1.x = f2u(sa1 + sb0 - 2.f * c0.y);
            o1.y = f2u(sa1 + sb1 - 2.f * c1.y);
            *reinterpret_cast<uint2*>(&d_dist[(size_t)(row0 + r) * N_ + col0 + 2 * l])     = o0;
            *reinterpret_cast<uint2*>(&d_dist[(size_t)(row0 + r + 1) * N_ + col0 + 2 * l]) = o1;

            unsigned g0 = __reduce_min_sync(FULLM, min(o0.x, o0.y));
            unsigned g1 = __reduce_min_sync(FULLM, min(o1.x, o1.y));
            if (l == 0) {
                d_gmin[(row0 + r)     * 32 + gidx] = g0;
                d_gmin[(row0 + r + 1) * 32 + gidx] = g1;
            }
        }
    }
}

// ---------------- selection: warp/row, tau from d_gmin, ONE sweep + ballot compact + insert ----------------
__device__ void knn_fallback(const unsigned* __restrict__ dr, int row, int l) {
    unsigned long long cur = ((unsigned long long)dr[l] << 32) | (unsigned)l;
    unsigned long long cmax; int cml;
    warp_argmax64(cur, l, cmax, cml);
    for (int ch = 1; ch < 64; ch++) {
        int col = ch * 32 + l;
        unsigned long long cand = ((unsigned long long)dr[col] << 32) | (unsigned)col;
        insert64(cand, cur, cmax, cml, l);
    }
    d_idx[row * K_ + l] = (int)(unsigned)cur;
}

__global__ void __launch_bounds__(256) select_kernel() {
    __shared__ unsigned long long buf[8][CAP_];
    const int tid = threadIdx.x, w = tid >> 5, l = tid & 31;
    const int row = blockIdx.x * 8 + w;
    const unsigned* dr = d_dist + (size_t)row * N_;

    unsigned tau = __reduce_max_sync(FULLM, d_gmin[row * 32 + l]);

    int cnt = 0;
    for (int j = 0; j < 16; j++) {
        uint4 v = *reinterpret_cast<const uint4*>(dr + 4 * l + 128 * j);
        unsigned e[4] = {v.x, v.y, v.z, v.w};
#pragma unroll
        for (int q = 0; q < 4; q++) {
            bool p = e[q] <= tau;
            unsigned m = __ballot_sync(FULLM, p);
            if (p) {
                int pos = cnt + __popc(m & ((1u << l) - 1u));
                if (pos < CAP_)
                    buf[w][pos] = ((unsigned long long)e[q] << 32) | (unsigned)(4 * l + 128 * j + q);
            }
            cnt += __popc(m);
        }
    }
    if (cnt > CAP_) { knn_fallback(dr, row, l); return; }

    unsigned long long cur = buf[w][l];
    unsigned long long cmax; int cml;
    warp_argmax64(cur, l, cmax, cml);
    for (int base = 32; base < cnt; base += 32) {
        int ix = base + l;
        unsigned long long cand = (ix < cnt) ? buf[w][ix] : ~0ull;
        insert64(cand, cur, cmax, cml, l);
    }
    d_idx[row * K_ + l] = (int)(unsigned)cur;
}

// ---------------- conv stage 1 (CIN=3): warp per point ----------------
__global__ void __launch_bounds__(256) conv3_kernel(const float* __restrict__ a,
                                                    const float* __restrict__ W) {
    __shared__ float snb[8][3][33];
    __shared__ float cs[64], css[64];
    const int tid = threadIdx.x, w = tid >> 5, l = tid & 31;
    const int pt = blockIdx.x * 8 + w;
    const int b  = pt >> 11, n = pt & (N_ - 1);
    const size_t pbase = (size_t)b * N_;

    if (tid < 64) { cs[tid] = 0.f; css[tid] = 0.f; }

    int nb = d_idx[(pbase + n) * K_ + l];
    const float* xp = a + (pbase + nb) * 3;
    snb[w][0][l] = xp[0]; snb[w][1][l] = xp[1]; snb[w][2][l] = xp[2];

    const float* cp = a + (pbase + n) * 3;
    float cx = cp[0], cy = cp[1], cz = cp[2];

    float wd[2][3], bse[2];
#pragma unroll
    for (int h = 0; h < 2; h++) {
        const float* wr = W + (2 * l + h) * 6;
        wd[h][0] = wr[0]; wd[h][1] = wr[1]; wd[h][2] = wr[2];
        bse[h] = cx * (wr[3] - wr[0]) + cy * (wr[4] - wr[1]) + cz * (wr[5] - wr[2]);
    }
    __syncwarp();
    __syncthreads();

    float s0 = 0.f, ss0 = 0.f, mx0 = -3.4e38f, mn0 = 3.4e38f;
    float s1 = 0.f, ss1 = 0.f, mx1 = -3.4e38f, mn1 = 3.4e38f;
#pragma unroll 8
    for (int r = 0; r < 32; r++) {
        float nx = snb[w][0][r], ny = snb[w][1][r], nz = snb[w][2][r];
        float y0 = fmaf(nz, wd[0][2], fmaf(ny, wd[0][1], nx * wd[0][0])) + bse[0];
        float y1 = fmaf(nz, wd[1][2], fmaf(ny, wd[1][1], nx * wd[1][0])) + bse[1];
        s0 += y0; ss0 = fmaf(y0, y0, ss0); mx0 = fmaxf(mx0, y0); mn0 = fminf(mn0, y0);
        s1 += y1; ss1 = fmaf(y1, y1, ss1); mx1 = fmaxf(mx1, y1); mn1 = fminf(mn1, y1);
    }
    size_t gi = (pbase + n) * 64 + 2 * l;
    d_mx[gi] = mx0; d_mx[gi + 1] = mx1;
    d_mn[gi] = mn0; d_mn[gi + 1] = mn1;

    atomicAdd(&cs [2 * l], s0);  atomicAdd(&cs [2 * l + 1], s1);
    atomicAdd(&css[2 * l], ss0); atomicAdd(&css[2 * l + 1], ss1);
    __syncthreads();
    if (tid < 64) {
        atomicAdd(&d_sum[tid], cs[tid]);
        atomicAdd(&d_ssq[tid], css[tid]);
    }
}

// ---------------- conv stage 2 (CIN=64): 8 points/block, 8x8 thread tile (R15 form) ----------------
constexpr int CP_ = 264;

__global__ void __launch_bounds__(256) conv64_kernel() {
    __shared__ __align__(16) float bufT[64][CP_];
    __shared__ __align__(16) float swd[64][68];
    __shared__ __align__(16) float swf[64][68];
    __shared__ float cen[8][64];
    __shared__ float bs[8][64];
    __shared__ int   sidx[256];
    __shared__ float cs[64], css[64];

    const float* x = (const float*)d_h;
    const int tid = threadIdx.x;
    const int pid = blockIdx.x;
    const int b   = pid >> 8;
    const int n0  = (pid & 255) * 8;
    const size_t base = (size_t)b * N_;

    if (tid < 64) { cs[tid] = 0.f; css[tid] = 0.f; }
    sidx[tid] = d_idx[(base + n0 + (tid >> 5)) * K_ + (tid & 31)];
    for (int v = tid; v < 4096; v += 256) {
        int c = v >> 6, o = v & 63;
        swd[c][o] = d_wd2[v];
        swf[c][o] = d_wf2[v];
    }
    for (int v = tid; v < 512; v += 256) {
        int p = v >> 6, c = v & 63;
        cen[p][c] = x[(base + n0 + p) * 64 + c];
    }
    __syncthreads();

    for (int v = tid; v < 4096; v += 256) {
        int c4 = v >> 8, r = v & 255;
        float4 f = *reinterpret_cast<const float4*>(x + (base + sidx[r]) * 64 + 4 * c4);
        bufT[4*c4+0][r] = f.x; bufT[4*c4+1][r] = f.y;
        bufT[4*c4+2][r] = f.z; bufT[4*c4+3][r] = f.w;
    }
    for (int v = tid; v < 512; v += 256) {
        int p = v >> 6, o = v & 63;
        float t = 0.f;
#pragma unroll 8
        for (int c = 0; c < 64; c++) t = fmaf(cen[p][c], swf[c][o], t);
        bs[p][o] = t;
    }
    __syncthreads();

    const int rg = tid >> 3, g = tid & 7;
    const int r0 = rg * 8;
    unsigned long long acc[8][4];
#pragma unroll
    for (int i = 0; i < 8; i++)
#pragma unroll
        for (int j = 0; j < 4; j++) acc[i][j] = 0ull;

#pragma unroll 2
    for (int c = 0; c < 64; c++) {
        float4 a0 = *reinterpret_cast<const float4*>(&bufT[c][r0]);
        float4 a1 = *reinterpret_cast<const float4*>(&bufT[c][r0 + 4]);
        ulonglong2 w01 = *reinterpret_cast<const ulonglong2*>(&swd[c][8 * g]);
        ulonglong2 w23 = *reinterpret_cast<const ulonglong2*>(&swd[c][8 * g + 4]);
        unsigned long long pa[8] = {pk2(a0.x), pk2(a0.y), pk2(a0.z), pk2(a0.w),
                                    pk2(a1.x), pk2(a1.y), pk2(a1.z), pk2(a1.w)};
#pragma unroll
        for (int i = 0; i < 8; i++) {
            fma2(acc[i][0], pa[i], w01.x);
            fma2(acc[i][1], pa[i], w01.y);
            fma2(acc[i][2], pa[i], w23.x);
            fma2(acc[i][3], pa[i], w23.y);
        }
    }
    __syncthreads();

    float* st0 = &bufT[0][0];
    float* st1 = st0 + 2048;
    float* st2 = st0 + 4096;
    float* st3 = st0 + 6144;

#pragma unroll
    for (int cp = 0; cp < 4; cp++) {
        float s_x = 0.f, ss_x = 0.f, mx_x = -3.4e38f, mn_x = 3.4e38f;
        float s_y = 0.f, ss_y = 0.f, mx_y = -3.4e38f, mn_y = 3.4e38f;
#pragma unroll
        for (int i = 0; i < 8; i++) {
            float2 v = up2(acc[i][cp]);
            s_x += v.x; ss_x = fmaf(v.x, v.x, ss_x); mx_x = fmaxf(mx_x, v.x); mn_x = fminf(mn_x, v.x);
            s_y += v.y; ss_y = fmaf(v.y, v.y, ss_y); mx_y = fmaxf(mx_y, v.y); mn_y = fminf(mn_y, v.y);
        }
        int o0 = 8 * g + 2 * cp, o1 = o0 + 1;
        st0[rg * 64 + o0] = s_x;  st0[rg * 64 + o1] = s_y;
        st1[rg * 64 + o0] = ss_x; st1[rg * 64 + o1] = ss_y;
        st2[rg * 64 + o0] = mx_x; st2[rg * 64 + o1] = mx_y;
        st3[rg * 64 + o0] = mn_x; st3[rg * 64 + o1] = mn_y;
    }
    __syncthreads();

    for (int v = tid; v < 512; v += 256) {
        int p = v >> 6, o = v & 63;
        float S = 0.f, SS = 0.f, MX = -3.4e38f, MN = 3.4e38f;
#pragma unroll
        for (int q = 0; q < 4; q++) {
            int rr = 4 * p + q;
            S  += st0[rr * 64 + o];
            SS += st1[rr * 64 + o];
            MX  = fmaxf(MX, st2[rr * 64 + o]);
            MN  = fminf(MN, st3[rr * 64 + o]);
        }
        float bb = bs[p][o];
        size_t gi = (base + n0 + p) * 64 + o;
        d_mx[gi] = MX + bb;
        d_mn[gi] = MN + bb;
        atomicAdd(&cs[o],  S + 32.f * bb);
        atomicAdd(&css[o], SS + 2.f * bb * S + 32.f * bb * bb);
    }
    __syncthreads();
    if (tid < 64) {
        atomicAdd(&d_sum2[tid], cs[tid]);
        atomicAdd(&d_ssq2[tid], css[tid]);
    }
}

// ---------------- passb+sqnorm fused, inline finalize (stage1 -> d_h, d_sq) ----------------
__global__ void __launch_bounds__(256) passb_sq_kernel(const float* __restrict__ gamma,
                                                       const float* __restrict__ beta) {
    const int tid = threadIdx.x, w = tid >> 5, l = tid & 31;
    const int pt = blockIdx.x * 8 + w;
    const float cntf = (float)(B_ * N_ * K_);

    int o = 2 * l;
    float mean0 = d_sum[o] / cntf,     mean1 = d_sum[o + 1] / cntf;
    float var0  = d_ssq[o] / cntf - mean0 * mean0;
    float var1  = d_ssq[o + 1] / cntf - mean1 * mean1;
    float sc0 = gamma[o]     * rsqrtf(var0 + 1e-5f);
    float sc1 = gamma[o + 1] * rsqrtf(var1 + 1e-5f);
    float sh0 = beta[o]     - mean0 * sc0;
    float sh1 = beta[o + 1] - mean1 * sc1;

    size_t gi = (size_t)pt * 64 + o;
    float2 mx = *reinterpret_cast<const float2*>(&d_mx[gi]);
    float2 mn = *reinterpret_cast<const float2*>(&d_mn[gi]);
    float y0 = sc0 * ((sc0 >= 0.f) ? mx.x : mn.x) + sh0;
    float y1 = sc1 * ((sc1 >= 0.f) ? mx.y : mn.y) + sh1;
    y0 = (y0 >= 0.f) ? y0 : 0.2f * y0;
    y1 = (y1 >= 0.f) ? y1 : 0.2f * y1;
    *reinterpret_cast<float2*>(&d_h[gi]) = make_float2(y0, y1);

    float s = y0 * y0 + y1 * y1;
#pragma unroll
    for (int off = 16; off > 0; off >>= 1) s += __shfl_down_sync(FULLM, s, off);
    if (l == 0) d_sq[pt] = s;
}

// ---------------- pass B final, inline finalize (stage2 -> out) ----------------
__global__ void passb_kernel(const float* __restrict__ gamma,
                             const float* __restrict__ beta,
                             float* __restrict__ out) {
    int e = blockIdx.x * 256 + threadIdx.x;
    if (e >= ROWS_ * CO_) return;
    int o = e & 63;
    const float cntf = (float)(B_ * N_ * K_);
    float mean = d_sum2[o] / cntf;
    float var  = d_ssq2[o] / cntf - mean * mean;
    float sc   = gamma[o] * rsqrtf(var + 1e-5f);
    float sh   = beta[o] - mean * sc;
    float v    = (sc >= 0.f) ? d_mx[e] : d_mn[e];
    float y    = sc * v + sh;
    out[e] = (y >= 0.f) ? y : 0.2f * y;
}

// ---------------- launch ----------------
extern "C" void kernel_launch(void* const* d_in, const int* in_sizes, int n_in,
                              void* d_out, int out_size) {
    const float* a  = (const float*)d_in[0];
    const float* W1 = (const float*)d_in[2];
    const float* g1 = (const float*)d_in[3];
    const float* b1 = (const float*)d_in[4];
    const float* W2 = (const float*)d_in[5];
    const float* g2 = (const float*)d_in[6];
    const float* b2 = (const float*)d_in[7];
    float* out = (float*)d_out;

    dim3 dg(ROWS_ / 128, 4);
    int  pts = ROWS_;

    prep_kernel<<<16, 256>>>(W2);                      // weights + zero both stat sets

    // stage 1 (C = 3)
    dist_kernel<3><<<dg, 256>>>(a);                    // sqnorms inline
    select_kernel<<<pts / 8, 256>>>();
    conv3_kernel<<<pts / 8, 256>>>(a, W1);
    passb_sq_kernel<<<pts / 8, 256>>>(g1, b1);         // inline finalize; d_h + d_sq

    // stage 2 (C = 64)
    dist_kernel<64><<<dg, 256>>>(nullptr);
    select_kernel<<<pts / 8, 256>>>();
    conv64_kernel<<<pts / 8, 256>>>();
    passb_kernel<<<(pts * CO_ + 255) / 256, 256>>>(g2, b2, out);   // inline finalize
}